// round 1
// baseline (speedup 1.0000x reference)
#include <cuda_runtime.h>
#include <math.h>

// Problem dimensions (fixed by the dataset)
#define Bsz   8
#define Tt    16
#define NCc   128
#define NcelL 64
#define DnL   64
#define Aa    4
#define HmL   128

// Pre-transposed MLP weights (written by a tiny setup kernel each launch).
// g_w1T[d][h] = msg_w1[h][d]   (so layer-1 inner-d loop reads contiguous rows)
// g_w2T[h][d] = msg_w2[d][h]   (so layer-2 inner-h loop reads contiguous rows)
__device__ float g_w1T[DnL * HmL];
__device__ float g_w2T[HmL * DnL];

__global__ void mg_transpose(const float* __restrict__ w1,
                             const float* __restrict__ w2) {
    int tid = blockIdx.x * blockDim.x + threadIdx.x;
    if (tid < HmL * DnL) {
        int h = tid / DnL, d = tid % DnL;       // w1 is [Hm][Dn]
        g_w1T[d * HmL + h] = w1[tid];
        int d2 = tid / HmL, h2 = tid % HmL;     // w2 is [Dn][Hm]
        g_w2T[h2 * DnL + d2] = w2[tid];
    }
}

// One CTA per (b, c) pair. State (h, W, hebbian) lives in shared memory for
// the whole T-loop. 256 threads.
__global__ __launch_bounds__(256, 2)
void mg_main(const float* __restrict__ x,     const float* __restrict__ h0,
             const float* __restrict__ W0,    const float* __restrict__ heb0,
             const float* __restrict__ nid,
             const float* __restrict__ injw,  const float* __restrict__ injb,
             const float* __restrict__ b1g,   const float* __restrict__ b2g,
             const float* __restrict__ wdl,   const float* __restrict__ dgl,
             const float* __restrict__ hdl,
             const int*   __restrict__ ipi,   const int*   __restrict__ opi,
             float* __restrict__ out) {
    extern __shared__ float sm[];
    float* sH    = sm;               // 4096  h (in-place: h -> h_in -> h_new)
    float* sW    = sH    + 4096;     // 4096  slow weights
    float* sHeb  = sW    + 4096;     // 4096  hebbian
    float* sM    = sHeb  + 4096;     // 4096  matmul-1 output
    float* sBig  = sM    + 4096;     // 8192  Wh (first 4096) then MLP hidden t
    float* sX    = sBig  + 8192;     // 64
    float* sInj  = sX    + 64;       // 256
    float* sInjB = sInj  + 256;      // 256
    float* sGam  = sInjB + 256;      // 64
    float* sHg   = sGam  + 64;       // 64
    float* sWg   = sHg   + 64;       // 64
    float* sB1   = sWg   + 64;       // 128
    float* sB2   = sB1   + 128;      // 64
    __shared__ int sIp[4], sOp[4];

    const int tid = threadIdx.x;
    const int c   = blockIdx.x / Bsz;     // c-major: co-resident CTAs share cell params in L2
    const int b   = blockIdx.x % Bsz;
    const int base = (b * NCc + c) * (NcelL * DnL);

    // ---- one-time setup ----
    if (tid < 64) {
        sGam[tid] = 0.5f / (1.0f + expf(-dgl[c * 64 + tid]));
        sHg[tid]  = 0.5f / (1.0f + expf(-hdl[c * 64 + tid]));
        sWg[tid]  = 0.5f / (1.0f + expf(-wdl[c * 64 + tid]));
        sB2[tid]  = b2g[tid];
    }
    if (tid < 128) sB1[tid] = b1g[tid];
    sInjB[tid] = injb[c * 256 + tid];
    if (tid < 4) { sIp[tid] = ipi[c * 4 + tid]; sOp[tid] = opi[c * 4 + tid]; }
    for (int i = tid; i < 4096; i += 256) {
        sH[i]   = h0[base + i];
        sW[i]   = W0[base + i];
        sHeb[i] = heb0[base + i];
    }
    __syncthreads();

    const int ig = tid >> 4;        // 0..15 (row-tile group)
    const int lg = tid & 15;        // 0..15 (col-tile group)
    const int i0 = ig * 4;

    for (int t = 0; t < Tt; ++t) {
        // ---- load x_t ----
        if (tid < 64) sX[tid] = x[((b * Tt + t) * NCc + c) * 64 + tid];
        __syncthreads();

        // ---- inject matvec (thread k = tid) + Wh = W + heb ----
        {
            const float4* wrow = reinterpret_cast<const float4*>(injw + (c * 256 + tid) * 64);
            float acc = sInjB[tid];
            #pragma unroll
            for (int q = 0; q < 16; q++) {
                float4 w  = __ldg(wrow + q);
                float4 xv = *reinterpret_cast<const float4*>(sX + 4 * q);
                acc = fmaf(w.x, xv.x, acc);
                acc = fmaf(w.y, xv.y, acc);
                acc = fmaf(w.z, xv.z, acc);
                acc = fmaf(w.w, xv.w, acc);
            }
            sInj[tid] = acc;
        }
        for (int i = tid; i < 4096; i += 256) sBig[i] = sW[i] + sHeb[i];
        __syncthreads();

        // ---- scatter-add onto input ports (serial per d-thread: handles dup ports) ----
        if (tid < 64) {
            #pragma unroll
            for (int a = 0; a < 4; a++) sH[sIp[a] * 64 + tid] += sInj[a * 64 + tid];
        }
        __syncthreads();

        // ---- matmul-1: m[i,d] = sum_j Wh[i,j] * h_in[j,d]  (4x4 tile/thread) ----
        {
            const int d0 = lg * 4;
            float acc[4][4];
            #pragma unroll
            for (int ii = 0; ii < 4; ii++)
                #pragma unroll
                for (int dd = 0; dd < 4; dd++) acc[ii][dd] = 0.0f;

            for (int j = 0; j < 64; j += 4) {
                float4 wr[4], hv[4];
                #pragma unroll
                for (int ii = 0; ii < 4; ii++)
                    wr[ii] = *reinterpret_cast<const float4*>(sBig + (i0 + ii) * 64 + j);
                #pragma unroll
                for (int jj = 0; jj < 4; jj++)
                    hv[jj] = *reinterpret_cast<const float4*>(sH + (j + jj) * 64 + d0);
                #pragma unroll
                for (int ii = 0; ii < 4; ii++) {
                    acc[ii][0] = fmaf(wr[ii].x, hv[0].x, acc[ii][0]);
                    acc[ii][1] = fmaf(wr[ii].x, hv[0].y, acc[ii][1]);
                    acc[ii][2] = fmaf(wr[ii].x, hv[0].z, acc[ii][2]);
                    acc[ii][3] = fmaf(wr[ii].x, hv[0].w, acc[ii][3]);
                    acc[ii][0] = fmaf(wr[ii].y, hv[1].x, acc[ii][0]);
                    acc[ii][1] = fmaf(wr[ii].y, hv[1].y, acc[ii][1]);
                    acc[ii][2] = fmaf(wr[ii].y, hv[1].z, acc[ii][2]);
                    acc[ii][3] = fmaf(wr[ii].y, hv[1].w, acc[ii][3]);
                    acc[ii][0] = fmaf(wr[ii].z, hv[2].x, acc[ii][0]);
                    acc[ii][1] = fmaf(wr[ii].z, hv[2].y, acc[ii][1]);
                    acc[ii][2] = fmaf(wr[ii].z, hv[2].z, acc[ii][2]);
                    acc[ii][3] = fmaf(wr[ii].z, hv[2].w, acc[ii][3]);
                    acc[ii][0] = fmaf(wr[ii].w, hv[3].x, acc[ii][0]);
                    acc[ii][1] = fmaf(wr[ii].w, hv[3].y, acc[ii][1]);
                    acc[ii][2] = fmaf(wr[ii].w, hv[3].z, acc[ii][2]);
                    acc[ii][3] = fmaf(wr[ii].w, hv[3].w, acc[ii][3]);
                }
            }
            #pragma unroll
            for (int ii = 0; ii < 4; ii++) {
                float4 v = make_float4(acc[ii][0], acc[ii][1], acc[ii][2], acc[ii][3]);
                *reinterpret_cast<float4*>(sM + (i0 + ii) * 64 + d0) = v;
            }
        }
        __syncthreads();

        // ---- MLP layer 1: t[i,h] = tanh(sum_d m[i,d]*w1T[d,h] + b1[h]), 4x8 tile ----
        {
            const int h0i = lg * 8;
            float acc[4][8];
            #pragma unroll
            for (int ii = 0; ii < 4; ii++)
                #pragma unroll
                for (int hh = 0; hh < 8; hh++) acc[ii][hh] = 0.0f;

            for (int d = 0; d < 64; d += 2) {
                float2 mv[4];
                #pragma unroll
                for (int ii = 0; ii < 4; ii++)
                    mv[ii] = *reinterpret_cast<const float2*>(sM + (i0 + ii) * 64 + d);
                float4 wa0 = __ldg(reinterpret_cast<const float4*>(g_w1T + d * HmL + h0i));
                float4 wb0 = __ldg(reinterpret_cast<const float4*>(g_w1T + d * HmL + h0i + 4));
                float4 wa1 = __ldg(reinterpret_cast<const float4*>(g_w1T + (d + 1) * HmL + h0i));
                float4 wb1 = __ldg(reinterpret_cast<const float4*>(g_w1T + (d + 1) * HmL + h0i + 4));
                #pragma unroll
                for (int ii = 0; ii < 4; ii++) {
                    float m0 = mv[ii].x, m1 = mv[ii].y;
                    acc[ii][0] = fmaf(m0, wa0.x, acc[ii][0]);
                    acc[ii][1] = fmaf(m0, wa0.y, acc[ii][1]);
                    acc[ii][2] = fmaf(m0, wa0.z, acc[ii][2]);
                    acc[ii][3] = fmaf(m0, wa0.w, acc[ii][3]);
                    acc[ii][4] = fmaf(m0, wb0.x, acc[ii][4]);
                    acc[ii][5] = fmaf(m0, wb0.y, acc[ii][5]);
                    acc[ii][6] = fmaf(m0, wb0.z, acc[ii][6]);
                    acc[ii][7] = fmaf(m0, wb0.w, acc[ii][7]);
                    acc[ii][0] = fmaf(m1, wa1.x, acc[ii][0]);
                    acc[ii][1] = fmaf(m1, wa1.y, acc[ii][1]);
                    acc[ii][2] = fmaf(m1, wa1.z, acc[ii][2]);
                    acc[ii][3] = fmaf(m1, wa1.w, acc[ii][3]);
                    acc[ii][4] = fmaf(m1, wb1.x, acc[ii][4]);
                    acc[ii][5] = fmaf(m1, wb1.y, acc[ii][5]);
                    acc[ii][6] = fmaf(m1, wb1.z, acc[ii][6]);
                    acc[ii][7] = fmaf(m1, wb1.w, acc[ii][7]);
                }
            }
            #pragma unroll
            for (int ii = 0; ii < 4; ii++) {
                #pragma unroll
                for (int hh = 0; hh < 8; hh++)
                    acc[ii][hh] = tanhf(acc[ii][hh] + sB1[h0i + hh]);
                float4 v0 = make_float4(acc[ii][0], acc[ii][1], acc[ii][2], acc[ii][3]);
                float4 v1 = make_float4(acc[ii][4], acc[ii][5], acc[ii][6], acc[ii][7]);
                *reinterpret_cast<float4*>(sBig + (i0 + ii) * 128 + h0i)     = v0;
                *reinterpret_cast<float4*>(sBig + (i0 + ii) * 128 + h0i + 4) = v1;
            }
        }
        __syncthreads();

        // ---- MLP layer 2 + gated state update: 4x4 tile/thread, sH in place ----
        {
            const int d0 = lg * 4;
            float acc[4][4];
            #pragma unroll
            for (int ii = 0; ii < 4; ii++)
                #pragma unroll
                for (int dd = 0; dd < 4; dd++) acc[ii][dd] = 0.0f;

            for (int h = 0; h < 128; h += 4) {
                float4 tv[4], wv[4];
                #pragma unroll
                for (int ii = 0; ii < 4; ii++)
                    tv[ii] = *reinterpret_cast<const float4*>(sBig + (i0 + ii) * 128 + h);
                #pragma unroll
                for (int hh = 0; hh < 4; hh++)
                    wv[hh] = __ldg(reinterpret_cast<const float4*>(g_w2T + (h + hh) * DnL + d0));
                #pragma unroll
                for (int ii = 0; ii < 4; ii++) {
                    acc[ii][0] = fmaf(tv[ii].x, wv[0].x, acc[ii][0]);
                    acc[ii][1] = fmaf(tv[ii].x, wv[0].y, acc[ii][1]);
                    acc[ii][2] = fmaf(tv[ii].x, wv[0].z, acc[ii][2]);
                    acc[ii][3] = fmaf(tv[ii].x, wv[0].w, acc[ii][3]);
                    acc[ii][0] = fmaf(tv[ii].y, wv[1].x, acc[ii][0]);
                    acc[ii][1] = fmaf(tv[ii].y, wv[1].y, acc[ii][1]);
                    acc[ii][2] = fmaf(tv[ii].y, wv[1].z, acc[ii][2]);
                    acc[ii][3] = fmaf(tv[ii].y, wv[1].w, acc[ii][3]);
                    acc[ii][0] = fmaf(tv[ii].z, wv[2].x, acc[ii][0]);
                    acc[ii][1] = fmaf(tv[ii].z, wv[2].y, acc[ii][1]);
                    acc[ii][2] = fmaf(tv[ii].z, wv[2].z, acc[ii][2]);
                    acc[ii][3] = fmaf(tv[ii].z, wv[2].w, acc[ii][3]);
                    acc[ii][0] = fmaf(tv[ii].w, wv[3].x, acc[ii][0]);
                    acc[ii][1] = fmaf(tv[ii].w, wv[3].y, acc[ii][1]);
                    acc[ii][2] = fmaf(tv[ii].w, wv[3].z, acc[ii][2]);
                    acc[ii][3] = fmaf(tv[ii].w, wv[3].w, acc[ii][3]);
                }
            }
            #pragma unroll
            for (int ii = 0; ii < 4; ii++) {
                const int i = i0 + ii;
                const float g = sGam[i];
                const float omg = 1.0f - g;
                float4 nv = __ldg(reinterpret_cast<const float4*>(nid + (c * 64 + i) * 64 + d0));
                float* hp = sH + i * 64 + d0;
                hp[0] = omg * hp[0] + g * tanhf(acc[ii][0] + sB2[d0 + 0] + nv.x);
                hp[1] = omg * hp[1] + g * tanhf(acc[ii][1] + sB2[d0 + 1] + nv.y);
                hp[2] = omg * hp[2] + g * tanhf(acc[ii][2] + sB2[d0 + 2] + nv.z);
                hp[3] = omg * hp[3] + g * tanhf(acc[ii][3] + sB2[d0 + 3] + nv.w);
            }
        }
        __syncthreads();

        // ---- readout (h_new) ----
        if (tid < 64) {
            float s = sH[sOp[0] * 64 + tid] + sH[sOp[1] * 64 + tid]
                    + sH[sOp[2] * 64 + tid] + sH[sOp[3] * 64 + tid];
            out[((b * Tt + t) * NCc + c) * 64 + tid] = s * 0.125f;  // (1/A)*A^-0.5
        }

        // ---- hebbian outer-product update + W decay: 4x4 tile/thread ----
        {
            const int j0 = lg * 4;
            float acc[4][4];
            #pragma unroll
            for (int ii = 0; ii < 4; ii++)
                #pragma unroll
                for (int jj = 0; jj < 4; jj++) acc[ii][jj] = 0.0f;

            for (int dq = 0; dq < 64; dq += 4) {
                float4 hi[4], hj[4];
                #pragma unroll
                for (int ii = 0; ii < 4; ii++)
                    hi[ii] = *reinterpret_cast<const float4*>(sH + (i0 + ii) * 64 + dq);
                #pragma unroll
                for (int jj = 0; jj < 4; jj++)
                    hj[jj] = *reinterpret_cast<const float4*>(sH + (j0 + jj) * 64 + dq);
                #pragma unroll
                for (int ii = 0; ii < 4; ii++)
                    #pragma unroll
                    for (int jj = 0; jj < 4; jj++) {
                        acc[ii][jj] = fmaf(hi[ii].x, hj[jj].x, acc[ii][jj]);
                        acc[ii][jj] = fmaf(hi[ii].y, hj[jj].y, acc[ii][jj]);
                        acc[ii][jj] = fmaf(hi[ii].z, hj[jj].z, acc[ii][jj]);
                        acc[ii][jj] = fmaf(hi[ii].w, hj[jj].w, acc[ii][jj]);
                    }
            }
            const float invd = 1.0f / 64.0f;   // (Dn^-0.5)^2
            #pragma unroll
            for (int ii = 0; ii < 4; ii++) {
                const int i = i0 + ii;
                const float hgv  = sHg[i];
                const float wdec = 1.0f - sWg[i];
                #pragma unroll
                for (int jj = 0; jj < 4; jj++) {
                    const int j = j0 + jj;
                    float v = (1.0f - hgv) * sHeb[i * 64 + j] + hgv * acc[ii][jj] * invd;
                    sHeb[i * 64 + j] = (i == j) ? 0.0f : v;
                    sW[i * 64 + j] *= wdec;
                }
            }
        }
        __syncthreads();
    }
}

extern "C" void kernel_launch(void* const* d_in, const int* in_sizes, int n_in,
                              void* d_out, int out_size) {
    const float* x    = (const float*)d_in[0];
    const float* h0   = (const float*)d_in[1];
    const float* W0   = (const float*)d_in[2];
    const float* heb0 = (const float*)d_in[3];
    const float* nid  = (const float*)d_in[4];
    const float* w1   = (const float*)d_in[5];
    const float* b1   = (const float*)d_in[6];
    const float* w2   = (const float*)d_in[7];
    const float* b2   = (const float*)d_in[8];
    const float* injw = (const float*)d_in[9];
    const float* injb = (const float*)d_in[10];
    const float* wdl  = (const float*)d_in[11];
    const float* dgl  = (const float*)d_in[12];
    const float* hdl  = (const float*)d_in[13];
    const int*   ipi  = (const int*)d_in[14];
    const int*   opi  = (const int*)d_in[15];
    float* out = (float*)d_out;

    const int smem_bytes = (4096 * 4 + 8192 + 64 + 256 + 256 + 64 + 64 + 64 + 128 + 64) * 4;
    cudaFuncSetAttribute(mg_main, cudaFuncAttributeMaxDynamicSharedMemorySize, smem_bytes);

    mg_transpose<<<32, 256>>>(w1, w2);
    mg_main<<<NCc * Bsz, 256, smem_bytes>>>(x, h0, W0, heb0, nid, injw, injb,
                                            b1, b2, wdl, dgl, hdl, ipi, opi, out);
}